// round 1
// baseline (speedup 1.0000x reference)
#include <cuda_runtime.h>
#include <cuda_bf16.h>
#include <math.h>

#define FULL_MASK 0xFFFFFFFFu

// Scratch for chosen FPS indices (bs*m <= 4*512 = 2048; headroom).
__device__ int g_qidx[8192];

// ---------------------------------------------------------------------------
// Mask dtype handling: the reference mask is boolean; the harness may hand it
// to us as uint8 (1B), int32, or float32. mask[b=0, j=0] is always True
// (lengths >= n/2 >= 1), so the first 4 bytes disambiguate:
//   0x3F800000 -> float32 (1.0f)
//   0x00000001 -> int32   (1)
//   0x01010101 -> uint8   (1,1,1,1)
// ---------------------------------------------------------------------------
__device__ __forceinline__ int mask_mode(const void* mask) {
    unsigned u0 = *(const unsigned*)mask;
    if (u0 == 0x3F800000u) return 2;   // f32
    if (u0 == 1u)          return 1;   // i32
    return 0;                          // byte
}
__device__ __forceinline__ bool mask_at(const void* mask, int mode, long idx) {
    if (mode == 0) return ((const unsigned char*)mask)[idx] != 0;
    if (mode == 1) return ((const int*)mask)[idx] != 0;
    return ((const float*)mask)[idx] != 0.0f;
}

// ---------------------------------------------------------------------------
// FPS kernel: one block per batch, 1024 threads, n = 2048 (2 cols/thread).
// Replicates the jax scan exactly:
//   chosen_t = farthest (recorded at loop top)
//   d        = where(mask, ||abq[b, farthest, :, :]||, -100)
//   distances = min(distances, d)      (init 1e8)
//   farthest  = argmax(distances)      (FIRST max -> lowest index on ties)
// ---------------------------------------------------------------------------
__global__ void __launch_bounds__(1024, 1)
fps_kernel(const float4* __restrict__ abq, const void* __restrict__ mask,
           const int* __restrict__ rand_start, int n, int m) {
    const int b    = blockIdx.x;
    const int tid  = threadIdx.x;
    const int nthr = blockDim.x;            // 1024

    extern __shared__ unsigned char smem[];
    unsigned char* s_mask = smem;                        // n bytes
    float* s_rval = (float*)(smem + n);                  // 32 floats
    int*   s_ridx = (int*)(s_rval + 32);                 // 32 ints
    int*   s_far  = s_ridx + 32;                         // 1 int

    const int  mode  = mask_mode(mask);
    const long mbase = (long)b * n;
    for (int j = tid; j < n; j += nthr)
        s_mask[j] = mask_at(mask, mode, mbase + j) ? 1 : 0;
    __syncthreads();

    // ---- initial farthest: index of k-th True, k = rand_start[b] % count ----
    if (tid < 32) {
        const int lane  = tid;
        const int chunk = (n + 31) / 32;     // 64 for n=2048
        const int base  = lane * chunk;
        int cnt = 0;
        for (int i = 0; i < chunk; i++) {
            int jj = base + i;
            if (jj < n) cnt += s_mask[jj];
        }
        int inc = cnt;
        #pragma unroll
        for (int off = 1; off < 32; off <<= 1) {
            int v = __shfl_up_sync(FULL_MASK, inc, off);
            if (lane >= off) inc += v;
        }
        const int total = __shfl_sync(FULL_MASK, inc, 31);
        const int k     = rand_start[b] % total;
        const int excl  = inc - cnt;
        if (k >= excl && k < inc) {
            int need = k - excl;
            for (int i = 0; i < chunk; i++) {
                int jj = base + i;
                if (jj < n && s_mask[jj]) {
                    if (need == 0) { *s_far = jj; break; }
                    need--;
                }
            }
        }
    }
    __syncthreads();
    int far = *s_far;

    // ---- main sequential loop ----
    const int j0 = tid;
    const int j1 = tid + nthr;               // n == 2*nthr assumed (2048/1024)
    float dist0 = 1e8f, dist1 = 1e8f;
    const bool vm0 = s_mask[j0] != 0;
    const bool vm1 = s_mask[j1] != 0;
    const int lane = tid & 31;
    const int warp = tid >> 5;

    for (int t = 0; t < m; t++) {
        if (tid == 0) g_qidx[b * m + t] = far;

        const float4* row = abq + ((size_t)b * n + (size_t)far) * (size_t)n;
        float4 v0 = __ldg(row + j0);
        float4 v1 = __ldg(row + j1);

        float d0 = vm0 ? sqrtf(v0.x*v0.x + v0.y*v0.y + v0.z*v0.z + v0.w*v0.w)
                       : -100.0f;
        float d1 = vm1 ? sqrtf(v1.x*v1.x + v1.y*v1.y + v1.z*v1.z + v1.w*v1.w)
                       : -100.0f;
        dist0 = fminf(dist0, d0);
        dist1 = fminf(dist1, d1);

        // thread-local argmax (tie -> lower index j0)
        float bv; int bi;
        if (dist1 > dist0) { bv = dist1; bi = j1; }
        else               { bv = dist0; bi = j0; }

        // warp argmax (tie -> lower index)
        #pragma unroll
        for (int off = 16; off > 0; off >>= 1) {
            float ov = __shfl_down_sync(FULL_MASK, bv, off);
            int   oi = __shfl_down_sync(FULL_MASK, bi, off);
            if (ov > bv || (ov == bv && oi < bi)) { bv = ov; bi = oi; }
        }
        if (lane == 0) { s_rval[warp] = bv; s_ridx[warp] = bi; }
        __syncthreads();

        // cross-warp argmax in warp 0 (32 warps -> 32 lanes)
        if (warp == 0) {
            bv = s_rval[lane];
            bi = s_ridx[lane];
            #pragma unroll
            for (int off = 16; off > 0; off >>= 1) {
                float ov = __shfl_down_sync(FULL_MASK, bv, off);
                int   oi = __shfl_down_sync(FULL_MASK, bi, off);
                if (ov > bv || (ov == bv && oi < bi)) { bv = ov; bi = oi; }
            }
            if (lane == 0) *s_far = bi;
        }
        __syncthreads();
        far = *s_far;
    }
}

// ---------------------------------------------------------------------------
// Gather sub_abq (float4, d=4) and sub_edges (float2, e=2) in one pass.
// idx enumerates (b, i, j) over bs*m*m.
// ---------------------------------------------------------------------------
__global__ void gather_pairs_kernel(const float4* __restrict__ abq,
                                    const float2* __restrict__ edges,
                                    float4* __restrict__ out_abq,
                                    float2* __restrict__ out_edges,
                                    int n, int m, int bs) {
    int idx = blockIdx.x * blockDim.x + threadIdx.x;
    int total = bs * m * m;
    if (idx >= total) return;
    int j = idx % m;
    int r = idx / m;
    int i = r % m;
    int b = r / m;
    int qi = g_qidx[b * m + i];
    int qj = g_qidx[b * m + j];
    size_t src = ((size_t)b * n + (size_t)qi) * (size_t)n + (size_t)qj;
    out_abq[idx]   = __ldg(abq + src);
    out_edges[idx] = __ldg(edges + src);
}

// ---------------------------------------------------------------------------
// Gather sub_vals (c floats per row, c%4==0 -> float4 chunks) and sub_mask.
// idx enumerates (b, i, chunk) over bs*m*(c/4).
// ---------------------------------------------------------------------------
__global__ void gather_small_kernel(const float4* __restrict__ vals4,
                                    const void* __restrict__ mask,
                                    float4* __restrict__ out_vals,
                                    float* __restrict__ out_mask,
                                    int n, int m, int bs, int c4) {
    int idx = blockIdx.x * blockDim.x + threadIdx.x;
    int total = bs * m * c4;
    if (idx >= total) return;
    int ch = idx % c4;
    int r  = idx / c4;
    int i  = r % m;
    int b  = r / m;
    int qi = g_qidx[b * m + i];
    out_vals[idx] = __ldg(vals4 + ((size_t)b * n + (size_t)qi) * (size_t)c4 + ch);
    if (ch == 0) {
        int mode = mask_mode(mask);
        out_mask[b * m + i] = mask_at(mask, mode, (long)b * n + qi) ? 1.0f : 0.0f;
    }
}

// ---------------------------------------------------------------------------
// Launch. Inputs (metadata order): abq_pairs f32 (bs,n,n,d=4), vals f32
// (bs,n,c=64), mask bool (bs,n), edges f32 (bs,n,n,e=2), rand_start i32 (bs).
// Output: concat of [sub_abq | sub_vals | sub_mask(1/0) | sub_edges] as f32.
// ---------------------------------------------------------------------------
extern "C" void kernel_launch(void* const* d_in, const int* in_sizes, int n_in,
                              void* d_out, int out_size) {
    const float4* abq   = (const float4*)d_in[0];
    const float4* vals4 = (const float4*)d_in[1];
    const void*   mask  = (const void*)d_in[2];
    const float2* edges = (const float2*)d_in[3];
    const int*    rnd   = (const int*)d_in[4];

    const int bs = in_sizes[4];                 // 4
    const int n  = in_sizes[2] / bs;            // 2048
    const int m  = n / 4;                       // round(0.25*n) = 512
    const int c  = in_sizes[1] / (bs * n);      // 64
    const int c4 = c / 4;                       // 16

    float* out = (float*)d_out;
    float4* out_abq   = (float4*)out;
    float*  out_vals_f = out + (size_t)bs * m * m * 4;
    float*  out_mask   = out_vals_f + (size_t)bs * m * c;
    float2* out_edges  = (float2*)(out_mask + (size_t)bs * m);

    // FPS: one block per batch, sequential m-step loop.
    size_t smem = (size_t)n + 32 * sizeof(float) + 32 * sizeof(int) + sizeof(int);
    fps_kernel<<<bs, 1024, smem>>>(abq, mask, rnd, n, m);

    // Gathers.
    int total_pairs = bs * m * m;
    gather_pairs_kernel<<<(total_pairs + 255) / 256, 256>>>(
        abq, edges, out_abq, out_edges, n, m, bs);

    int total_small = bs * m * c4;
    gather_small_kernel<<<(total_small + 255) / 256, 256>>>(
        vals4, mask, (float4*)out_vals_f, out_mask, n, m, bs, c4);
}

// round 2
// speedup vs baseline: 2.1567x; 2.1567x over previous
#include <cuda_runtime.h>
#include <cuda_bf16.h>
#include <math.h>

#define FULL_MASK 0xFFFFFFFFu

// Scratch: chosen FPS indices (bs*m <= 4*512) and the encoded distance matrix
// (bs*n*n = 4*2048*2048 uint32 = 64 MB; fits in GB300's ~126 MB L2).
__device__ int      g_qidx[8192];
__device__ unsigned g_dm[4L * 2048 * 2048];

// ---------------------------------------------------------------------------
// Mask dtype handling (bool may arrive as u8 / i32 / f32; mask[0] is True).
// ---------------------------------------------------------------------------
__device__ __forceinline__ int mask_mode(const void* mask) {
    unsigned u0 = *(const unsigned*)mask;
    if (u0 == 0x3F800000u) return 2;   // f32
    if (u0 == 1u)          return 1;   // i32
    return 0;                          // byte
}
__device__ __forceinline__ bool mask_at(const void* mask, int mode, long idx) {
    if (mode == 0) return ((const unsigned char*)mask)[idx] != 0;
    if (mode == 1) return ((const int*)mask)[idx] != 0;
    return ((const float*)mask)[idx] != 0.0f;
}

// Monotone (order-preserving) float -> uint32 encoding.
__device__ __forceinline__ unsigned enc_f32(float f) {
    unsigned u = __float_as_uint(f);
    unsigned s = (unsigned)((int)u >> 31);        // all-ones if negative
    return u ^ (s | 0x80000000u);
}

// ---------------------------------------------------------------------------
// Precompute: g_dm[b,i,j] = enc( mask[b,j] ? ||abq[b,i,j,:]|| : -100 ).
// One thread per 4 consecutive j (64B load / 16B store, fully coalesced).
// ---------------------------------------------------------------------------
__global__ void precompute_kernel(const float4* __restrict__ abq,
                                  const void* __restrict__ mask,
                                  int n, int total4) {
    int idx = blockIdx.x * blockDim.x + threadIdx.x;
    if (idx >= total4) return;
    const int nq = n >> 2;
    int j4 = idx % nq;
    int r  = idx / nq;
    int i  = r % n;       (void)i;
    int b  = r / n;

    const int mode = mask_mode(mask);
    const float4* src = abq + (size_t)idx * 4;
    unsigned out[4];
    #pragma unroll
    for (int k = 0; k < 4; k++) {
        float4 v = __ldg(src + k);
        float nrm = sqrtf(v.x*v.x + v.y*v.y + v.z*v.z + v.w*v.w);
        bool mk = mask_at(mask, mode, (long)b * n + j4 * 4 + k);
        out[k] = enc_f32(mk ? nrm : -100.0f);
    }
    ((uint4*)g_dm)[idx] = make_uint4(out[0], out[1], out[2], out[3]);
}

// ---------------------------------------------------------------------------
// FPS: one block per batch, 512 threads, 4 j's per thread (blocked layout so
// lane order == j order for first-occurrence tie-breaks).
// Per iter: 1 uint4 L2 load, 4 umin, local argmax, REDUX warp argmax,
// ONE barrier, redundant per-warp final reduce (double-buffered smem slots).
// ---------------------------------------------------------------------------
__global__ void __launch_bounds__(512, 1)
fps_kernel(const void* __restrict__ mask, const int* __restrict__ rand_start,
           int n, int m) {
    const int b    = blockIdx.x;
    const int tid  = threadIdx.x;
    const int nthr = blockDim.x;            // 512
    const int lane = tid & 31;
    const int warp = tid >> 5;               // 0..15

    extern __shared__ unsigned char smem[];
    unsigned char* s_mask = smem;                         // n bytes
    unsigned* s_key = (unsigned*)(smem + ((n + 7) & ~7)); // [2][16]
    int*      s_idx = (int*)(s_key + 32);                 // [2][16]
    int*      s_far = s_idx + 32;

    // Stage mask (needed only for the initial k-th-valid index).
    const int  mode  = mask_mode(mask);
    const long mbase = (long)b * n;
    for (int j = tid; j < n; j += nthr)
        s_mask[j] = mask_at(mask, mode, mbase + j) ? 1 : 0;
    __syncthreads();

    // Initial farthest = index of k-th True, k = rand_start[b] % count.
    if (tid < 32) {
        const int chunk = (n + 31) / 32;
        const int base  = lane * chunk;
        int cnt = 0;
        for (int i = 0; i < chunk; i++) {
            int jj = base + i;
            if (jj < n) cnt += s_mask[jj];
        }
        int inc = cnt;
        #pragma unroll
        for (int off = 1; off < 32; off <<= 1) {
            int v = __shfl_up_sync(FULL_MASK, inc, off);
            if (lane >= off) inc += v;
        }
        const int total = __shfl_sync(FULL_MASK, inc, 31);
        const int k     = rand_start[b] % total;
        const int excl  = inc - cnt;
        if (k >= excl && k < inc) {
            int need = k - excl;
            for (int i = 0; i < chunk; i++) {
                int jj = base + i;
                if (jj < n && s_mask[jj]) {
                    if (need == 0) { *s_far = jj; break; }
                    need--;
                }
            }
        }
    }
    __syncthreads();
    int far = *s_far;

    // Encoded running distances (init enc(1e8)).
    const unsigned E_INIT = enc_f32(1e8f);
    uint4 dist = make_uint4(E_INIT, E_INIT, E_INIT, E_INIT);

    const uint4* dmb = (const uint4*)(g_dm) + (size_t)b * n * (n >> 2);

    for (int t = 0; t < m; t++) {
        if (tid == 0) g_qidx[b * m + t] = far;

        // Row read: 8 KB from L2 (whole dm fits in L2 after precompute).
        uint4 v = __ldg(dmb + (size_t)far * (n >> 2) + tid);
        dist.x = min(dist.x, v.x);
        dist.y = min(dist.y, v.y);
        dist.z = min(dist.z, v.z);
        dist.w = min(dist.w, v.w);

        // Local argmax over 4 (tie -> lowest j).
        unsigned bk = dist.x; int bj = 0;
        if (dist.y > bk) { bk = dist.y; bj = 1; }
        if (dist.z > bk) { bk = dist.z; bj = 2; }
        if (dist.w > bk) { bk = dist.w; bj = 3; }
        bj += tid << 2;

        // Warp argmax via REDUX; tie -> lowest lane == lowest j (blocked).
        unsigned mk   = __reduce_max_sync(FULL_MASK, bk);
        unsigned ball = __ballot_sync(FULL_MASK, bk == mk);
        int src       = __ffs(ball) - 1;
        int wj        = __shfl_sync(FULL_MASK, bj, src);
        const int buf = t & 1;
        if (lane == 0) { s_key[buf * 16 + warp] = mk; s_idx[buf * 16 + warp] = wj; }
        __syncthreads();

        // Redundant final reduce in EVERY warp (no second barrier needed:
        // next iter writes the other buffer, and its own barrier fences it).
        unsigned k2 = 0; int j2 = 0;
        if (lane < 16) { k2 = s_key[buf * 16 + lane]; j2 = s_idx[buf * 16 + lane]; }
        unsigned mk2   = __reduce_max_sync(FULL_MASK, k2);
        unsigned ball2 = __ballot_sync(FULL_MASK, k2 == mk2);
        int src2       = __ffs(ball2) - 1;
        far            = __shfl_sync(FULL_MASK, j2, src2);
    }
}

// ---------------------------------------------------------------------------
// Gather sub_abq (float4) + sub_edges (float2).
// ---------------------------------------------------------------------------
__global__ void gather_pairs_kernel(const float4* __restrict__ abq,
                                    const float2* __restrict__ edges,
                                    float4* __restrict__ out_abq,
                                    float2* __restrict__ out_edges,
                                    int n, int m, int bs) {
    int idx = blockIdx.x * blockDim.x + threadIdx.x;
    int total = bs * m * m;
    if (idx >= total) return;
    int j = idx % m;
    int r = idx / m;
    int i = r % m;
    int b = r / m;
    int qi = g_qidx[b * m + i];
    int qj = g_qidx[b * m + j];
    size_t src = ((size_t)b * n + (size_t)qi) * (size_t)n + (size_t)qj;
    out_abq[idx]   = __ldg(abq + src);
    out_edges[idx] = __ldg(edges + src);
}

// ---------------------------------------------------------------------------
// Gather sub_vals (float4 chunks) + sub_mask.
// ---------------------------------------------------------------------------
__global__ void gather_small_kernel(const float4* __restrict__ vals4,
                                    const void* __restrict__ mask,
                                    float4* __restrict__ out_vals,
                                    float* __restrict__ out_mask,
                                    int n, int m, int bs, int c4) {
    int idx = blockIdx.x * blockDim.x + threadIdx.x;
    int total = bs * m * c4;
    if (idx >= total) return;
    int ch = idx % c4;
    int r  = idx / c4;
    int i  = r % m;
    int b  = r / m;
    int qi = g_qidx[b * m + i];
    out_vals[idx] = __ldg(vals4 + ((size_t)b * n + (size_t)qi) * (size_t)c4 + ch);
    if (ch == 0) {
        int mode = mask_mode(mask);
        out_mask[b * m + i] = mask_at(mask, mode, (long)b * n + qi) ? 1.0f : 0.0f;
    }
}

// ---------------------------------------------------------------------------
// Launch. Inputs: abq_pairs f32 (bs,n,n,4), vals f32 (bs,n,64), mask bool
// (bs,n), edges f32 (bs,n,n,2), rand_start i32 (bs).
// Output: [sub_abq | sub_vals | sub_mask | sub_edges] as f32.
// ---------------------------------------------------------------------------
extern "C" void kernel_launch(void* const* d_in, const int* in_sizes, int n_in,
                              void* d_out, int out_size) {
    const float4* abq   = (const float4*)d_in[0];
    const float4* vals4 = (const float4*)d_in[1];
    const void*   mask  = (const void*)d_in[2];
    const float2* edges = (const float2*)d_in[3];
    const int*    rnd   = (const int*)d_in[4];

    const int bs = in_sizes[4];                 // 4
    const int n  = in_sizes[2] / bs;            // 2048
    const int m  = n / 4;                       // 512
    const int c  = in_sizes[1] / (bs * n);      // 64
    const int c4 = c / 4;

    float* out = (float*)d_out;
    float4* out_abq    = (float4*)out;
    float*  out_vals_f = out + (size_t)bs * m * m * 4;
    float*  out_mask   = out_vals_f + (size_t)bs * m * c;
    float2* out_edges  = (float2*)(out_mask + (size_t)bs * m);

    // 1) Precompute encoded masked-distance matrix (bandwidth-bound, ~50us).
    int total4 = bs * n * (n / 4);
    precompute_kernel<<<(total4 + 255) / 256, 256>>>(abq, mask, n, total4);

    // 2) Sequential FPS on the L2-resident encoded matrix.
    size_t smem = (size_t)((n + 7) & ~7) + 32 * sizeof(unsigned)
                + 32 * sizeof(int) + sizeof(int);
    fps_kernel<<<bs, 512, smem>>>(mask, rnd, n, m);

    // 3) Output gathers (~6us).
    int total_pairs = bs * m * m;
    gather_pairs_kernel<<<(total_pairs + 255) / 256, 256>>>(
        abq, edges, out_abq, out_edges, n, m, bs);

    int total_small = bs * m * c4;
    gather_small_kernel<<<(total_small + 255) / 256, 256>>>(
        vals4, mask, (float4*)out_vals_f, out_mask, n, m, bs, c4);
}